// round 1
// baseline (speedup 1.0000x reference)
#include <cuda_runtime.h>

// HausdorffDTLoss:
//   pred, target: [4,1,256,256] fp32
//   pred_dt   = distance_field(pred)   (stop-grad, exact EDT)
//   target_dt = distance_field(target)
//   loss = mean( (pred-target)^2 * (pred_dt^2 + target_dt^2) )
//
// distance_field(img) = where(any(fg), edt(fg) + edt(~fg), 0),  fg = img > 0.5
// edt(mask) = sqrt(min(F, BIG)),  F = 1D min-plus sq transform along H then W
// Since exactly one of edt(fg), edt(~fg) is nonzero per pixel:
//   dt^2 = min(F_fg, BIG) + min(F_~fg, BIG)   (no sqrt needed)

#define BIGF 1e10f

#define B_N 4
#define HW 256
#define IMG (HW * HW)            // 65536
#define TOTAL (B_N * IMG)        // 262144

// Scratch (device globals; allocation in kernel_launch is forbidden)
// P1: vertical-pass output, TRANSPOSED layout [in][b][mask][x][y]
__device__ float g_P1[2 * B_N * 2 * IMG];
// D2: combined clamped squared distance field [in][b][y][x]
__device__ float g_D2[2 * B_N * IMG];
__device__ int g_fgany[8];       // [in*4 + b]
__device__ double g_accum;

__global__ void init_kernel() {
    int t = threadIdx.x;
    if (t < 8) g_fgany[t] = 0;
    if (t == 0) g_accum = 0.0;
}

// ---------------------------------------------------------------------------
// Stage 1: vertical min-plus transform (along y) for both masks.
// Block = (in, b, x-tile of 8 columns). Threads = 256 (one per y).
// smem rows are padded with BIG on both sides so the windowed scan needs no
// bounds checks. Output written transposed ([x][y]) so writes here and reads
// in stage 2 are both coalesced.
// ---------------------------------------------------------------------------
__global__ __launch_bounds__(256) void stage1_kernel(
    const float* __restrict__ pred, const float* __restrict__ target)
{
    __shared__ float sF[8][768];   // fg mask:  0 where img<=0.5, BIG where img>0.5
    __shared__ float sN[8][768];   // ~fg mask: 0 where img>0.5,  BIG where img<=0.5

    int bid = blockIdx.x;          // 0..255
    int xt  = bid & 31;
    int b   = (bid >> 5) & 3;
    int in  = bid >> 7;
    int x0  = xt * 8;
    int tid = threadIdx.x;

    // Pad [0,256) and [512,768) with BIG
    for (int idx = tid; idx < 4096; idx += 256) {
        int k = idx >> 9;
        int o = idx & 511;
        int off = (o < 256) ? o : (o + 256);
        sF[k][off] = BIGF;
        sN[k][off] = BIGF;
    }

    const float* img = (in == 0 ? pred : target) + b * IMG;

    int anyfg = 0;
    #pragma unroll
    for (int it = 0; it < 8; ++it) {
        int idx = it * 256 + tid;
        int j = idx >> 3;          // y
        int k = idx & 7;           // column within tile
        float v = img[j * HW + x0 + k];   // coalesced (32B sectors)
        bool fg = v > 0.5f;
        anyfg |= (int)fg;
        sF[k][256 + j] = fg ? BIGF : 0.0f;
        sN[k][256 + j] = fg ? 0.0f : BIGF;
    }
    int blk_any = __syncthreads_or(anyfg);
    if (tid == 0 && blk_any) atomicOr(&g_fgany[in * 4 + b], 1);

    int y = tid;
    #pragma unroll 1
    for (int k = 0; k < 8; ++k) {
        const float* F = &sF[k][256];
        const float* N = &sN[k][256];
        float mF = F[y];
        float mN = N[y];
        float d2 = 1.0f, st = 3.0f;
        for (int d = 1; d < 256; ++d) {
            if (d2 >= mF && d2 >= mN) break;   // no farther candidate can win
            mF = fminf(mF, fminf(F[y - d], F[y + d]) + d2);
            mN = fminf(mN, fminf(N[y - d], N[y + d]) + d2);
            d2 += st; st += 2.0f;
        }
        int base = ((in * 4 + b) * 2) * IMG + (x0 + k) * HW + y;  // [in][b][0][x][y]
        g_P1[base]       = mF;          // coalesced across threads (y)
        g_P1[base + IMG] = mN;          // mask 1
    }
}

// ---------------------------------------------------------------------------
// Stage 2: horizontal min-plus transform (along x), clamp to BIG, combine
// fg + ~fg into the squared distance field.
// Block = (in, b, y-tile of 8 rows). Threads = 256 (one per x).
// ---------------------------------------------------------------------------
__global__ __launch_bounds__(256) void stage2_kernel()
{
    __shared__ float sF[8][768];
    __shared__ float sN[8][768];

    int bid = blockIdx.x;
    int yt  = bid & 31;
    int b   = (bid >> 5) & 3;
    int in  = bid >> 7;
    int y0  = yt * 8;
    int tid = threadIdx.x;

    for (int idx = tid; idx < 4096; idx += 256) {
        int k = idx >> 9;
        int o = idx & 511;
        int off = (o < 256) ? o : (o + 256);
        sF[k][off] = BIGF;
        sN[k][off] = BIGF;
    }

    const float* P0  = g_P1 + ((in * 4 + b) * 2) * IMG;  // mask 0, layout [x][y]
    const float* P1m = P0 + IMG;                          // mask 1

    #pragma unroll
    for (int it = 0; it < 8; ++it) {
        int idx = it * 256 + tid;
        int j = idx >> 3;          // x (column index in original image)
        int k = idx & 7;           // row within tile
        sF[k][256 + j] = P0 [j * HW + y0 + k];   // coalesced (transposed layout)
        sN[k][256 + j] = P1m[j * HW + y0 + k];
    }
    __syncthreads();

    int x = tid;
    float* D = g_D2 + (in * 4 + b) * IMG;
    #pragma unroll 1
    for (int k = 0; k < 8; ++k) {
        const float* F = &sF[k][256];
        const float* N = &sN[k][256];
        float mF = F[x];
        float mN = N[x];
        float d2 = 1.0f, st = 3.0f;
        for (int d = 1; d < 256; ++d) {
            if (d2 >= mF && d2 >= mN) break;
            mF = fminf(mF, fminf(F[x - d], F[x + d]) + d2);
            mN = fminf(mN, fminf(N[x - d], N[x + d]) + d2);
            d2 += st; st += 2.0f;
        }
        // dt^2 = min(F_fg,BIG) + min(F_~fg,BIG)  (cross term is exactly 0)
        D[(y0 + k) * HW + x] = fminf(mF, BIGF) + fminf(mN, BIGF);
    }
}

// ---------------------------------------------------------------------------
// Loss: elementwise (p-t)^2 * (dp + dt) with fg_any masking, double reduction.
// ---------------------------------------------------------------------------
__global__ __launch_bounds__(256) void loss_kernel(
    const float* __restrict__ pred, const float* __restrict__ target)
{
    __shared__ double sred[256];
    int tid = threadIdx.x;
    double acc = 0.0;
    #pragma unroll
    for (int s = 0; s < 4; ++s) {
        int i = blockIdx.x * 1024 + s * 256 + tid;
        int b = i >> 16;
        float p = pred[i];
        float t = target[i];
        float e = (p - t) * (p - t);
        float dp = g_fgany[b]     ? g_D2[i]         : 0.0f;
        float dt = g_fgany[4 + b] ? g_D2[TOTAL + i] : 0.0f;
        acc += (double)e * (double)(dp + dt);
    }
    sred[tid] = acc;
    __syncthreads();
    #pragma unroll
    for (int s2 = 128; s2 > 0; s2 >>= 1) {
        if (tid < s2) sred[tid] += sred[tid + s2];
        __syncthreads();
    }
    if (tid == 0) atomicAdd(&g_accum, sred[0]);
}

__global__ void finalize_kernel(float* __restrict__ out) {
    out[0] = (float)(g_accum * (1.0 / (double)TOTAL));
}

extern "C" void kernel_launch(void* const* d_in, const int* in_sizes, int n_in,
                              void* d_out, int out_size) {
    const float* pred   = (const float*)d_in[0];
    const float* target = (const float*)d_in[1];
    float* out = (float*)d_out;

    init_kernel<<<1, 32>>>();
    stage1_kernel<<<256, 256>>>(pred, target);
    stage2_kernel<<<256, 256>>>();
    loss_kernel<<<256, 256>>>(pred, target);
    finalize_kernel<<<1, 1>>>(out);
}

// round 2
// speedup vs baseline: 1.1372x; 1.1372x over previous
#include <cuda_runtime.h>

// HausdorffDTLoss, [4,1,256,256] fp32 inputs.
// loss = mean( (pred-target)^2 * (pred_dt^2 + target_dt^2) )
// dt^2 = min(F_fg,BIG) + min(F_~fg,BIG)  (exactly one EDT is 0 per pixel),
// F = separable 1D min-plus squared-distance transform (y-pass then x-pass),
// computed with an early-exit outward window (bit-exact vs brute force since
// every candidate is the identical fp32 expression f[j] + (i-j)^2, f >= 0).
//
// Two launches:
//   stage1: vertical pass for both images/masks, output transposed; fg_any.
//   stage2: horizontal pass fused with the loss reduction + finalize.
// Device globals are zero-init at load; the last stage2 block resets all
// state, so each call starts clean (graph-replay safe, no init kernel).

#define BIGF 1e10f
#define HW 256
#define IMG 65536
#define TOTAL 262144

// Vertical-pass output, layout [in(2)][b(4)][mask(2)][x][y]
__device__ float g_P1[2 * 4 * 2 * IMG];
__device__ int g_fgany[8];          // [in*4 + b], zero-init / self-reset
__device__ double g_accum;          // zero-init / self-reset
__device__ unsigned int g_counter;  // zero-init / self-reset

// ---------------------------------------------------------------------------
// Stage 1: vertical min-plus (along y), both masks of one image per block.
// Block = (in, b, 8-column tile). 256 threads (one per y).
// Rows padded with BIG (255 left / 255 right) so scans need no bounds checks.
// Output written transposed ([x][y]) so stage-2 reads are near-contiguous.
// ---------------------------------------------------------------------------
__global__ __launch_bounds__(256) void stage1_kernel(
    const float* __restrict__ pred, const float* __restrict__ target)
{
    __shared__ __align__(16) float s[16 * 766];  // rows 0..7: fg, 8..15: ~fg

    int bid = blockIdx.x;          // 0..255
    int xt  = bid & 31;
    int b   = (bid >> 5) & 3;
    int in  = bid >> 7;
    int x0  = xt * 8;
    int tid = threadIdx.x;

    // Pads only: per row, [0,255) and [511,766)
    for (int idx = tid; idx < 16 * 510; idx += 256) {
        int row = idx / 510;
        int o   = idx - row * 510;
        int off = (o < 255) ? o : (o + 256);
        s[row * 766 + off] = BIGF;
    }

    const float* img = (in == 0 ? pred : target) + b * IMG;

    int anyfg = 0;
    #pragma unroll
    for (int it = 0; it < 8; ++it) {
        int idx = it * 256 + tid;
        int j = idx >> 3;          // y
        int k = idx & 7;           // column within tile
        float v = img[j * HW + x0 + k];
        bool fg = v > 0.5f;
        anyfg |= (int)fg;
        s[k * 766 + 255 + j]       = fg ? BIGF : 0.0f;
        s[(8 + k) * 766 + 255 + j] = fg ? 0.0f : BIGF;
    }
    int blk_any = __syncthreads_or(anyfg);
    if (tid == 0 && blk_any) atomicOr(&g_fgany[in * 4 + b], 1);

    int y = tid;
    #pragma unroll 1
    for (int k = 0; k < 8; ++k) {
        const float* F = s + k * 766 + 255;
        const float* N = s + (8 + k) * 766 + 255;
        float mF = F[y];
        float mN = N[y];
        float d2 = 1.0f, st = 3.0f;
        #pragma unroll 1
        for (int d = 1; d < 256; ++d) {
            if (d2 >= mF && d2 >= mN) break;   // no farther candidate can win
            mF = fminf(mF, fminf(F[y - d], F[y + d]) + d2);
            mN = fminf(mN, fminf(N[y - d], N[y + d]) + d2);
            d2 += st; st += 2.0f;
        }
        int base = ((in * 4 + b) * 2) * IMG + (x0 + k) * HW + y;
        g_P1[base]       = mF;          // coalesced across threads (y)
        g_P1[base + IMG] = mN;
    }
}

// ---------------------------------------------------------------------------
// Stage 2 (fused): horizontal min-plus for BOTH images + loss + reduction.
// Block = (b, 4-row tile). 256 threads (one per x). 4 arrays per row
// (pred-fg, pred-~fg, tgt-fg, tgt-~fg) = 16 x 766 floats smem.
// Last block finalizes out[0] and resets all device state.
// ---------------------------------------------------------------------------
__global__ __launch_bounds__(256) void stage2_kernel(
    const float* __restrict__ pred, const float* __restrict__ target,
    float* __restrict__ out)
{
    __shared__ __align__(16) float s[16 * 766];

    int bid = blockIdx.x;          // 0..255
    int yt  = bid & 63;
    int b   = bid >> 6;
    int y0  = yt * 4;
    int tid = threadIdx.x;

    for (int idx = tid; idx < 16 * 510; idx += 256) {
        int row = idx / 510;
        int o   = idx - row * 510;
        int off = (o < 255) ? o : (o + 256);
        s[row * 766 + off] = BIGF;
    }

    // Load 4 arrays x 4 rows x 256 x from transposed P1
    #pragma unroll
    for (int c = 0; c < 4; ++c) {       // c = in*2 + mask
        int in = c >> 1, mask = c & 1;
        const float* P = g_P1 + (((in * 4 + b) * 2) + mask) * IMG;
        #pragma unroll
        for (int it = 0; it < 4; ++it) {
            int idx = it * 256 + tid;
            int j = idx >> 2;           // x
            int k = idx & 3;            // row within tile
            s[(c * 4 + k) * 766 + 255 + j] = P[j * HW + y0 + k];
        }
    }
    __syncthreads();

    int x = tid;
    int fgp = g_fgany[b];
    int fgt = g_fgany[4 + b];
    const float* pr = pred + b * IMG;
    const float* tg = target + b * IMG;

    double acc = 0.0;
    #pragma unroll 1
    for (int k = 0; k < 4; ++k) {
        float dsq0, dsq1;
        #pragma unroll
        for (int in = 0; in < 2; ++in) {
            const float* F = s + ((in * 2 + 0) * 4 + k) * 766 + 255;
            const float* N = s + ((in * 2 + 1) * 4 + k) * 766 + 255;
            float mF = F[x];
            float mN = N[x];
            float d2 = 1.0f, st = 3.0f;
            #pragma unroll 1
            for (int d = 1; d < 256; ++d) {
                if (d2 >= mF && d2 >= mN) break;
                mF = fminf(mF, fminf(F[x - d], F[x + d]) + d2);
                mN = fminf(mN, fminf(N[x - d], N[x + d]) + d2);
                d2 += st; st += 2.0f;
            }
            float dv = fminf(mF, BIGF) + fminf(mN, BIGF);
            if (in == 0) dsq0 = dv; else dsq1 = dv;
        }
        float dp = fgp ? dsq0 : 0.0f;
        float dt = fgt ? dsq1 : 0.0f;
        float p = pr[(y0 + k) * HW + x];
        float t = tg[(y0 + k) * HW + x];
        float e = (p - t) * (p - t);
        acc += (double)e * (double)(dp + dt);
    }

    // Block reduction: warp shuffles, then smem (reused) for 8 warp sums.
    #pragma unroll
    for (int o = 16; o > 0; o >>= 1)
        acc += __shfl_down_sync(0xFFFFFFFFu, acc, o);

    __syncthreads();                    // done reading s; safe to reuse
    double* ws = (double*)s;
    int wid = tid >> 5, lane = tid & 31;
    if (lane == 0) ws[wid] = acc;
    __syncthreads();

    if (tid == 0) {
        double bsum = 0.0;
        #pragma unroll
        for (int w = 0; w < 8; ++w) bsum += ws[w];
        atomicAdd(&g_accum, bsum);
        __threadfence();
        unsigned done = atomicAdd(&g_counter, 1u);
        if (done == gridDim.x - 1) {
            double tot = atomicAdd(&g_accum, 0.0);   // L2-coherent read
            out[0] = (float)(tot * (1.0 / (double)TOTAL));
            // Self-reset state for the next (graph-replayed) call.
            g_accum = 0.0;
            g_counter = 0u;
            #pragma unroll
            for (int i = 0; i < 8; ++i) g_fgany[i] = 0;
        }
    }
}

extern "C" void kernel_launch(void* const* d_in, const int* in_sizes, int n_in,
                              void* d_out, int out_size) {
    const float* pred   = (const float*)d_in[0];
    const float* target = (const float*)d_in[1];
    float* out = (float*)d_out;

    stage1_kernel<<<256, 256>>>(pred, target);
    stage2_kernel<<<256, 256>>>(pred, target, out);
}